// round 6
// baseline (speedup 1.0000x reference)
#include <cuda_runtime.h>
#include <cmath>

#define NMAX 20000

__device__ float g_PHI[NMAX * 32];
__device__ float g_ENV[NMAX];
__device__ float g_F[NMAX * 192];

// ---------------------------------------------------------------------------
// Edge kernel: scatter env-weighted RBF vector + env into per-node sums.
// ---------------------------------------------------------------------------
__global__ void edge_kernel(const float* __restrict__ dist,
                            const int* __restrict__ nb, int E,
                            float mu0, float delta, float inv_delta,
                            float beta, float c2, float q)
{
    int e = blockIdx.x * blockDim.x + threadIdx.x;
    if (e >= E) return;
    float d = dist[e];
    int j = nb[e];
    float env = 0.0f;
    if (d < 5.0f) env = 0.5f * (__cosf(0.62831853071795864769f * d) + 1.0f);
    atomicAdd(&g_ENV[j], env);

    float t = __expf(-d);
    int r0 = (int)floorf((t - mu0) * inv_delta + 0.5f);
    r0 = max(0, min(31, r0));
    float u0 = t - (mu0 + delta * (float)r0);
    float p0 = env * __expf(-beta * u0 * u0);
    float* phr = g_PHI + (size_t)j * 32;
    const float THR = 1e-6f;
    if (p0 > THR) atomicAdd(&phr[r0], p0);

    float w = __expf(c2 * (t - (mu0 + delta * ((float)r0 + 0.5f))));
    float p = p0;
    for (int r = r0 + 1; r < 32; ++r) {
        p *= w; w *= q;
        if (p <= THR) break;
        atomicAdd(&phr[r], p);
    }
    w = __expf(-c2 * (t - (mu0 + delta * ((float)r0 - 0.5f))));
    p = p0;
    for (int r = r0 - 1; r >= 0; --r) {
        p *= w; w *= q;
        if (p <= THR) break;
        atomicAdd(&phr[r], p);
    }
}

// ---------------------------------------------------------------------------
// Coefficient kernel: F[n, o] = env[n]*bd[o] + sum_r Wd[o, r] * phi[n, r]
// ---------------------------------------------------------------------------
__global__ void coeff_kernel(const float* __restrict__ Wd,
                             const float* __restrict__ bd, int N)
{
    __shared__ float ph[32];
    int n = blockIdx.x;
    int o = threadIdx.x;
    if (o < 32) ph[o] = g_PHI[(size_t)n * 32 + o];
    __syncthreads();
    float acc = g_ENV[n] * bd[o];
    const float4* w = (const float4*)(Wd + (size_t)o * 32);
    #pragma unroll
    for (int r4 = 0; r4 < 8; ++r4) {
        float4 wv = w[r4];
        acc += wv.x * ph[4 * r4] + wv.y * ph[4 * r4 + 1]
             + wv.z * ph[4 * r4 + 2] + wv.w * ph[4 * r4 + 3];
    }
    g_F[(size_t)n * 192 + o] = acc;
}

// ---------------------------------------------------------------------------
// f32x2 packed FMA helpers
// ---------------------------------------------------------------------------
__device__ __forceinline__ void ffma2(unsigned long long& d,
                                      unsigned long long a,
                                      unsigned long long b)
{
    asm("fma.rn.f32x2 %0, %1, %2, %0;" : "+l"(d) : "l"(a), "l"(b));
}
__device__ __forceinline__ float sum2(unsigned long long v)
{
    float lo, hi;
    asm("mov.b64 {%0, %1}, %2;" : "=f"(lo), "=f"(hi) : "l"(v));
    return lo + hi;
}

__device__ __forceinline__ void decomp9(const float x[9], float* iso,
                                        float a[3], float s[5])
{
    float m = (x[0] + x[4] + x[8]) * (1.0f / 3.0f);
    *iso = m;
    a[0] = 0.5f * (x[1] - x[3]);
    a[1] = 0.5f * (x[2] - x[6]);
    a[2] = 0.5f * (x[5] - x[7]);
    s[0] = x[0] - m;
    s[1] = 0.5f * (x[1] + x[3]);
    s[2] = 0.5f * (x[2] + x[6]);
    s[3] = x[4] - m;
    s[4] = 0.5f * (x[5] + x[7]);
}

__device__ __forceinline__ void build9(float iso, const float a[3],
                                       const float s[5], float Y[9])
{
    Y[0] = iso + s[0];        Y[1] = a[0] + s[1];       Y[2] = a[1] + s[2];
    Y[3] = s[1] - a[0];       Y[4] = iso + s[3];        Y[5] = a[2] + s[4];
    Y[6] = s[2] - a[1];       Y[7] = s[4] - a[2];       Y[8] = iso - s[0] - s[3];
}

// ---------------------------------------------------------------------------
// Node kernel: 8 warps/block, 4 nodes/warp, plane-major comps (R4 layout).
// Double-buffered X/output staging to hide LDG latency.
// ---------------------------------------------------------------------------
#define NWARP 8
#define WROW 68
#define PLANE 68
#define CPSZ (9 * PLANE)          // 612 per node
#define OFF_W    0                // 6 * 64 * 68 = 26112
#define OFF_WARP 26112
#define WSZ      3604             // cp 4*612=2448 | xs 2*576=1152 | pad 4
#define SMEM_FLOATS (OFF_WARP + NWARP * WSZ)   // 54944 floats = 219,776 B

template<int NC>
__device__ __forceinline__ void sector_pass(const float* __restrict__ Wsec,
                                            const float* __restrict__ cp,
                                            int lane,
                                            unsigned long long acc[NC][2][4])
{
    const float* w0 = Wsec + lane * WROW;
    const float* w1 = Wsec + (lane + 32) * WROW;
    #pragma unroll 8
    for (int j = 0; j < 16; ++j) {
        ulonglong2 wv0 = *(const ulonglong2*)(w0 + 4 * j);
        ulonglong2 wv1 = *(const ulonglong2*)(w1 + 4 * j);
        #pragma unroll
        for (int n = 0; n < 4; ++n) {
            const float* base = cp + n * CPSZ + 4 * j;
            #pragma unroll
            for (int k = 0; k < NC; ++k) {
                ulonglong2 m = *(const ulonglong2*)(base + k * PLANE);
                ffma2(acc[k][0][n], wv0.x, m.x);
                ffma2(acc[k][0][n], wv0.y, m.y);
                ffma2(acc[k][1][n], wv1.x, m.x);
                ffma2(acc[k][1][n], wv1.y, m.y);
            }
        }
    }
}

__device__ __forceinline__ void stage_x(const float* __restrict__ X,
                                        int node, int N, int lane, float* xs)
{
    if (node < N) {
        const float4* src = (const float4*)(X + (size_t)node * 576);
        float4* dst = (float4*)xs;
        #pragma unroll
        for (int i = 0; i < 5; ++i) {
            int idx = lane + 32 * i;
            if (idx < 144) dst[idx] = src[idx];
        }
    }
}

__global__ __launch_bounds__(256, 1)
void node_kernel(const float* __restrict__ X,
    const float* __restrict__ WIa, const float* __restrict__ WAa, const float* __restrict__ WSa,
    const float* __restrict__ WIb, const float* __restrict__ WAb, const float* __restrict__ WSb,
    float* __restrict__ out, int N)
{
    extern __shared__ float sm[];
    int tid  = threadIdx.x;
    int warp = tid >> 5;
    int lane = tid & 31;

    // ---- stage weights (once per block), A,S,I order per mix stage ----
    {
        const float* Ws[6] = {WAa, WSa, WIa, WAb, WSb, WIb};
        #pragma unroll
        for (int m = 0; m < 6; ++m) {
            const float* src = Ws[m];
            float* dst = sm + OFF_W + m * (64 * WROW);
            for (int idx = tid; idx < 4096; idx += 256)
                dst[(idx >> 6) * WROW + (idx & 63)] = src[idx];
        }
    }
    __syncthreads();

    float* cp  = sm + OFF_WARP + warp * WSZ;      // 4 * 612
    float* xs0 = cp + 4 * CPSZ;                    // 576
    float* xs1 = xs0 + 576;                        // 576

    const float* smWA_a = sm + OFF_W + 0 * (64 * WROW);
    const float* smWS_a = sm + OFF_W + 1 * (64 * WROW);
    const float* smWI_a = sm + OFF_W + 2 * (64 * WROW);
    const float* smWA_b = sm + OFF_W + 3 * (64 * WROW);
    const float* smWS_b = sm + OFF_W + 4 * (64 * WROW);
    const float* smWI_b = sm + OFF_W + 5 * (64 * WROW);

    int Q = (N + 3) >> 2;
    int gw = blockIdx.x * NWARP + warp;
    int step = gridDim.x * NWARP;

    for (int q = gw; q < Q; q += step) {
        int n0 = q << 2;

        // ---- double-buffered: stage X(n+1) while decomposing X(n) ----
        stage_x(X, n0, N, lane, xs0);
        __syncwarp();
        #pragma unroll
        for (int n = 0; n < 4; ++n) {
            float* cur = (n & 1) ? xs1 : xs0;
            float* nxt = (n & 1) ? xs0 : xs1;
            if (n < 3) stage_x(X, n0 + n + 1, N, lane, nxt);

            float* cpn = cp + n * CPSZ;
            #pragma unroll
            for (int h = 0; h < 2; ++h) {
                int c = lane + 32 * h;
                float x[9];
                #pragma unroll
                for (int k = 0; k < 9; ++k) x[k] = cur[c * 9 + k];
                float f = 0.0f;
                #pragma unroll
                for (int k = 0; k < 9; ++k) f += x[k] * x[k];
                float sc = __fdividef(1.0f, f + 1.0f);
                #pragma unroll
                for (int k = 0; k < 9; ++k) x[k] *= sc;
                float iso, a[3], s[5];
                decomp9(x, &iso, a, s);
                cpn[0 * PLANE + c] = a[0];
                cpn[1 * PLANE + c] = a[1];
                cpn[2 * PLANE + c] = a[2];
                cpn[3 * PLANE + c] = s[0];
                cpn[4 * PLANE + c] = s[1];
                cpn[5 * PLANE + c] = s[2];
                cpn[6 * PLANE + c] = s[3];
                cpn[7 * PLANE + c] = s[4];
                cpn[8 * PLANE + c] = iso;
            }
            __syncwarp();
        }

        // ---- load precomputed coefficients F ----
        float fI[2][4], fA[2][4], fS[2][4];
        #pragma unroll
        for (int n = 0; n < 4; ++n) {
            int node = min(n0 + n, N - 1);
            const float* Fn = g_F + (size_t)node * 192;
            #pragma unroll
            for (int h = 0; h < 2; ++h) {
                int c = lane + 32 * h;
                fI[h][n] = Fn[c];
                fA[h][n] = Fn[64 + c];
                fS[h][n] = Fn[128 + c];
            }
        }

        // ---- pre mixes (sector-split) ----
        float yi[2][4], ya[3][2][4], ys[5][2][4];
        {
            unsigned long long accA[3][2][4] = {};
            sector_pass<3>(smWA_a, cp, lane, accA);
            #pragma unroll
            for (int k = 0; k < 3; ++k)
                #pragma unroll
                for (int h = 0; h < 2; ++h)
                    #pragma unroll
                    for (int n = 0; n < 4; ++n) ya[k][h][n] = sum2(accA[k][h][n]);
        }
        {
            unsigned long long accS[5][2][4] = {};
            sector_pass<5>(smWS_a, cp + 3 * PLANE, lane, accS);
            #pragma unroll
            for (int k = 0; k < 5; ++k)
                #pragma unroll
                for (int h = 0; h < 2; ++h)
                    #pragma unroll
                    for (int n = 0; n < 4; ++n) ys[k][h][n] = sum2(accS[k][h][n]);
        }
        {
            unsigned long long accI[1][2][4] = {};
            sector_pass<1>(smWI_a, cp + 8 * PLANE, lane, accI);
            #pragma unroll
            for (int h = 0; h < 2; ++h)
                #pragma unroll
                for (int n = 0; n < 4; ++n) yi[h][n] = sum2(accI[0][h][n]);
        }
        __syncwarp();

        // ---- sandwich: Z = YM + MY, normalize, decompose -> overwrite comps
        #pragma unroll
        for (int n = 0; n < 4; ++n) {
            float* cpn = cp + n * CPSZ;
            #pragma unroll
            for (int h = 0; h < 2; ++h) {
                int c = lane + 32 * h;
                float Y[9], M[9];
                float av[3] = {ya[0][h][n], ya[1][h][n], ya[2][h][n]};
                float sv[5] = {ys[0][h][n], ys[1][h][n], ys[2][h][n],
                               ys[3][h][n], ys[4][h][n]};
                build9(yi[h][n], av, sv, Y);
                float mi = fI[h][n] * cpn[8 * PLANE + c];
                float A[3] = {fA[h][n] * cpn[0 * PLANE + c],
                              fA[h][n] * cpn[1 * PLANE + c],
                              fA[h][n] * cpn[2 * PLANE + c]};
                float S[5] = {fS[h][n] * cpn[3 * PLANE + c],
                              fS[h][n] * cpn[4 * PLANE + c],
                              fS[h][n] * cpn[5 * PLANE + c],
                              fS[h][n] * cpn[6 * PLANE + c],
                              fS[h][n] * cpn[7 * PLANE + c]};
                build9(mi, A, S, M);
                float Z[9];
                #pragma unroll
                for (int i = 0; i < 3; ++i)
                    #pragma unroll
                    for (int jj = 0; jj < 3; ++jj) {
                        float acc = 0.0f;
                        #pragma unroll
                        for (int k = 0; k < 3; ++k)
                            acc += Y[i * 3 + k] * M[k * 3 + jj]
                                 + M[i * 3 + k] * Y[k * 3 + jj];
                        Z[i * 3 + jj] = acc;
                    }
                float nrm = 0.0f;
                #pragma unroll
                for (int k = 0; k < 9; ++k) { float v = Z[k] + 1.0f; nrm += v * v; }
                float inv = __fdividef(1.0f, nrm);
                #pragma unroll
                for (int k = 0; k < 9; ++k) Z[k] *= inv;
                float iso, a2[3], s2[5];
                decomp9(Z, &iso, a2, s2);
                cpn[0 * PLANE + c] = a2[0];
                cpn[1 * PLANE + c] = a2[1];
                cpn[2 * PLANE + c] = a2[2];
                cpn[3 * PLANE + c] = s2[0];
                cpn[4 * PLANE + c] = s2[1];
                cpn[5 * PLANE + c] = s2[2];
                cpn[6 * PLANE + c] = s2[3];
                cpn[7 * PLANE + c] = s2[4];
                cpn[8 * PLANE + c] = iso;
            }
        }
        __syncwarp();

        // ---- post mixes ----
        {
            unsigned long long accA[3][2][4] = {};
            sector_pass<3>(smWA_b, cp, lane, accA);
            #pragma unroll
            for (int k = 0; k < 3; ++k)
                #pragma unroll
                for (int h = 0; h < 2; ++h)
                    #pragma unroll
                    for (int n = 0; n < 4; ++n) ya[k][h][n] = sum2(accA[k][h][n]);
        }
        {
            unsigned long long accS[5][2][4] = {};
            sector_pass<5>(smWS_b, cp + 3 * PLANE, lane, accS);
            #pragma unroll
            for (int k = 0; k < 5; ++k)
                #pragma unroll
                for (int h = 0; h < 2; ++h)
                    #pragma unroll
                    for (int n = 0; n < 4; ++n) ys[k][h][n] = sum2(accS[k][h][n]);
        }
        {
            unsigned long long accI[1][2][4] = {};
            sector_pass<1>(smWI_b, cp + 8 * PLANE, lane, accI);
            #pragma unroll
            for (int h = 0; h < 2; ++h)
                #pragma unroll
                for (int n = 0; n < 4; ++n) yi[h][n] = sum2(accI[0][h][n]);
        }
        __syncwarp();

        // ---- output: O = Y2 + Y2@Y2, double-buffered staging + store ----
        #pragma unroll
        for (int n = 0; n < 4; ++n) {
            int node = n0 + n;
            float* buf = (n & 1) ? xs1 : xs0;
            #pragma unroll
            for (int h = 0; h < 2; ++h) {
                int c = lane + 32 * h;
                float av[3] = {ya[0][h][n], ya[1][h][n], ya[2][h][n]};
                float sv[5] = {ys[0][h][n], ys[1][h][n], ys[2][h][n],
                               ys[3][h][n], ys[4][h][n]};
                float Y2[9];
                build9(yi[h][n], av, sv, Y2);
                float* od = buf + c * 9;
                #pragma unroll
                for (int i = 0; i < 3; ++i)
                    #pragma unroll
                    for (int jj = 0; jj < 3; ++jj) {
                        float acc = Y2[i * 3 + jj];
                        #pragma unroll
                        for (int k = 0; k < 3; ++k)
                            acc += Y2[i * 3 + k] * Y2[k * 3 + jj];
                        od[i * 3 + jj] = acc;
                    }
            }
            __syncwarp();
            if (node < N) {
                float4* dst = (float4*)(out + (size_t)node * 576);
                const float4* src = (const float4*)buf;
                #pragma unroll
                for (int i = 0; i < 5; ++i) {
                    int idx = lane + 32 * i;
                    if (idx < 144) dst[idx] = src[idx];
                }
            }
            // no syncwarp needed here: next iteration writes the OTHER buffer;
            // the syncwarp after its build orders reuse of this one.
        }
        __syncwarp();
    }
}

// ---------------------------------------------------------------------------
extern "C" void kernel_launch(void* const* d_in, const int* in_sizes, int n_in,
                              void* d_out, int out_size)
{
    const float* X    = (const float*)d_in[0];
    const float* dist = (const float*)d_in[1];
    const int*   nb   = (const int*)d_in[2];
    const float* WIa  = (const float*)d_in[3];
    const float* WAa  = (const float*)d_in[4];
    const float* WSa  = (const float*)d_in[5];
    const float* WIb  = (const float*)d_in[6];
    const float* WAb  = (const float*)d_in[7];
    const float* WSb  = (const float*)d_in[8];
    const float* Wd   = (const float*)d_in[9];
    const float* bd   = (const float*)d_in[10];
    float* out = (float*)d_out;

    int N = in_sizes[0] / 576;
    int E = in_sizes[1];

    void* phi_ptr = nullptr;
    void* env_ptr = nullptr;
    cudaGetSymbolAddress(&phi_ptr, g_PHI);
    cudaGetSymbolAddress(&env_ptr, g_ENV);
    cudaMemsetAsync(phi_ptr, 0, sizeof(float) * (size_t)N * 32, 0);
    cudaMemsetAsync(env_ptr, 0, sizeof(float) * (size_t)N, 0);

    double e5    = exp(-5.0);
    double delta = (1.0 - e5) / 31.0;
    double bb    = (2.0 / 32.0) * (1.0 - e5);
    double beta  = 1.0 / (bb * bb);
    float  c2    = (float)(2.0 * beta * delta);
    float  qf    = (float)exp(-2.0 * beta * delta * delta);

    edge_kernel<<<(E + 255) / 256, 256>>>(dist, nb, E,
        (float)e5, (float)delta, (float)(1.0 / delta), (float)beta, c2, qf);
    coeff_kernel<<<N, 192>>>(Wd, bd, N);

    static int smem_set = 0;
    if (!smem_set) {
        cudaFuncSetAttribute(node_kernel,
                             cudaFuncAttributeMaxDynamicSharedMemorySize,
                             SMEM_FLOATS * sizeof(float));
        smem_set = 1;
    }
    node_kernel<<<148, 256, SMEM_FLOATS * sizeof(float)>>>(
        X, WIa, WAa, WSa, WIb, WAb, WSb, out, N);
}

// round 7
// speedup vs baseline: 1.0019x; 1.0019x over previous
#include <cuda_runtime.h>
#include <cmath>

#define NMAX 20000

__device__ float g_PHI[NMAX * 32];
__device__ float g_ENV[NMAX];

// ---------------------------------------------------------------------------
// Edge kernel: scatter env-weighted RBF vector + env into per-node sums.
// All 32 phi values via monotone-decay recurrence from the nearest center
// (superexponential decay -> far bins underflow to exact 0), then one
// red.global.add.v4.f32 per nonzero 16B group (~4-5 vector REDs per edge
// instead of ~15 scalar REDs).
// ---------------------------------------------------------------------------
__global__ void edge_kernel(const float* __restrict__ dist,
                            const int* __restrict__ nb, int E,
                            float mu0, float delta, float inv_delta,
                            float beta, float c2, float q)
{
    int e = blockIdx.x * blockDim.x + threadIdx.x;
    if (e >= E) return;
    float d = dist[e];
    int j = nb[e];
    float env = 0.0f;
    if (d < 5.0f) env = 0.5f * (__cosf(0.62831853071795864769f * d) + 1.0f);
    asm volatile("red.global.add.f32 [%0], %1;"
                 :: "l"(&g_ENV[j]), "f"(env) : "memory");

    float t = __expf(-d);
    int r0 = (int)floorf((t - mu0) * inv_delta + 0.5f);
    r0 = max(0, min(31, r0));
    float u0 = t - (mu0 + delta * (float)r0);
    float p0 = env * __expf(-beta * u0 * u0);

    float p[32];
    #pragma unroll
    for (int r = 0; r < 32; ++r) p[r] = 0.0f;
    p[r0] = p0;

    // upward sweep (ratios < 1, shrinking: Gaussian decay)
    {
        float w = __expf(c2 * (t - (mu0 + delta * ((float)r0 + 0.5f))));
        float pp = p0;
        for (int r = r0 + 1; r < 32; ++r) {
            pp *= w; w *= q;
            if (pp <= 1e-12f) break;
            p[r] = pp;
        }
    }
    // downward sweep
    {
        float w = __expf(-c2 * (t - (mu0 + delta * ((float)r0 - 0.5f))));
        float pp = p0;
        for (int r = r0 - 1; r >= 0; --r) {
            pp *= w; w *= q;
            if (pp <= 1e-12f) break;
            p[r] = pp;
        }
    }

    float* phr = g_PHI + (size_t)j * 32;
    #pragma unroll
    for (int g = 0; g < 8; ++g) {
        float a0 = p[4 * g], a1 = p[4 * g + 1], a2 = p[4 * g + 2], a3 = p[4 * g + 3];
        if (a0 + a1 + a2 + a3 > 0.0f) {
            asm volatile("red.global.add.v4.f32 [%0], {%1, %2, %3, %4};"
                         :: "l"(phr + 4 * g), "f"(a0), "f"(a1), "f"(a2), "f"(a3)
                         : "memory");
        }
    }
}

// ---------------------------------------------------------------------------
// f32x2 packed FMA helpers
// ---------------------------------------------------------------------------
__device__ __forceinline__ void ffma2(unsigned long long& d,
                                      unsigned long long a,
                                      unsigned long long b)
{
    asm("fma.rn.f32x2 %0, %1, %2, %0;" : "+l"(d) : "l"(a), "l"(b));
}
__device__ __forceinline__ float sum2(unsigned long long v)
{
    float lo, hi;
    asm("mov.b64 {%0, %1}, %2;" : "=f"(lo), "=f"(hi) : "l"(v));
    return lo + hi;
}

__device__ __forceinline__ void decomp9(const float x[9], float* iso,
                                        float a[3], float s[5])
{
    float m = (x[0] + x[4] + x[8]) * (1.0f / 3.0f);
    *iso = m;
    a[0] = 0.5f * (x[1] - x[3]);
    a[1] = 0.5f * (x[2] - x[6]);
    a[2] = 0.5f * (x[5] - x[7]);
    s[0] = x[0] - m;
    s[1] = 0.5f * (x[1] + x[3]);
    s[2] = 0.5f * (x[2] + x[6]);
    s[3] = x[4] - m;
    s[4] = 0.5f * (x[5] + x[7]);
}

__device__ __forceinline__ void build9(float iso, const float a[3],
                                       const float s[5], float Y[9])
{
    Y[0] = iso + s[0];        Y[1] = a[0] + s[1];       Y[2] = a[1] + s[2];
    Y[3] = s[1] - a[0];       Y[4] = iso + s[3];        Y[5] = a[2] + s[4];
    Y[6] = s[2] - a[1];       Y[7] = s[4] - a[2];       Y[8] = iso - s[0] - s[3];
}

// ---------------------------------------------------------------------------
// Node kernel (R4 artifact, byte-identical): 8 warps/block, 4 nodes/warp,
// plane-major comps, in-loop coefficient GEMV, weights staged in smem.
// ---------------------------------------------------------------------------
#define NWARP 8
#define WROW 68
#define PLANE 68
#define CPSZ (9 * PLANE)          // 612 per node
#define OFF_W    0                // 6 * 64 * 68 = 26112
#define OFF_WDT  26112            // WdT[32][192] = 6144
#define OFF_WARP 32256
#define WSZ      3160             // cp 4*612=2448 | xs 576 | phi 4*33=132 | pad
#define SMEM_FLOATS (OFF_WARP + NWARP * WSZ)   // 57,536 floats = 230,144 B

template<int NC>
__device__ __forceinline__ void sector_pass(const float* __restrict__ Wsec,
                                            const float* __restrict__ cp,
                                            int lane,
                                            unsigned long long acc[NC][2][4])
{
    const float* w0 = Wsec + lane * WROW;
    const float* w1 = Wsec + (lane + 32) * WROW;
    #pragma unroll 4
    for (int j = 0; j < 16; ++j) {
        ulonglong2 wv0 = *(const ulonglong2*)(w0 + 4 * j);
        ulonglong2 wv1 = *(const ulonglong2*)(w1 + 4 * j);
        #pragma unroll
        for (int n = 0; n < 4; ++n) {
            const float* base = cp + n * CPSZ + 4 * j;
            #pragma unroll
            for (int k = 0; k < NC; ++k) {
                ulonglong2 m = *(const ulonglong2*)(base + k * PLANE);
                ffma2(acc[k][0][n], wv0.x, m.x);
                ffma2(acc[k][0][n], wv0.y, m.y);
                ffma2(acc[k][1][n], wv1.x, m.x);
                ffma2(acc[k][1][n], wv1.y, m.y);
            }
        }
    }
}

__global__ __launch_bounds__(256, 1)
void node_kernel(const float* __restrict__ X,
    const float* __restrict__ WIa, const float* __restrict__ WAa, const float* __restrict__ WSa,
    const float* __restrict__ WIb, const float* __restrict__ WAb, const float* __restrict__ WSb,
    const float* __restrict__ Wd, const float* __restrict__ bd,
    float* __restrict__ out, int N)
{
    extern __shared__ float sm[];
    int tid  = threadIdx.x;
    int warp = tid >> 5;
    int lane = tid & 31;

    // ---- stage weights (once per block) ----
    {
        const float* Ws[6] = {WAa, WSa, WIa, WAb, WSb, WIb};   // A,S,I order
        #pragma unroll
        for (int m = 0; m < 6; ++m) {
            const float* src = Ws[m];
            float* dst = sm + OFF_W + m * (64 * WROW);
            for (int idx = tid; idx < 4096; idx += 256)
                dst[(idx >> 6) * WROW + (idx & 63)] = src[idx];
        }
        for (int idx = tid; idx < 6144; idx += 256) {
            int gc = idx >> 5, r = idx & 31;
            sm[OFF_WDT + r * 192 + gc] = Wd[idx];
        }
    }
    // bias hoist (constant over nodes)
    float bI0 = bd[lane],        bI1 = bd[lane + 32];
    float bA0 = bd[64 + lane],   bA1 = bd[96 + lane];
    float bS0 = bd[128 + lane],  bS1 = bd[160 + lane];
    __syncthreads();

    float* cp   = sm + OFF_WARP + warp * WSZ;        // 4 * 612
    float* xs   = cp + 4 * CPSZ;                      // 576
    float* phis = xs + 576;                           // 4 * 33

    const float* smWA_a = sm + OFF_W + 0 * (64 * WROW);
    const float* smWS_a = sm + OFF_W + 1 * (64 * WROW);
    const float* smWI_a = sm + OFF_W + 2 * (64 * WROW);
    const float* smWA_b = sm + OFF_W + 3 * (64 * WROW);
    const float* smWS_b = sm + OFF_W + 4 * (64 * WROW);
    const float* smWI_b = sm + OFF_W + 5 * (64 * WROW);
    const float* smWdT  = sm + OFF_WDT;

    int Q = (N + 3) >> 2;
    int gw = blockIdx.x * NWARP + warp;
    int step = gridDim.x * NWARP;

    for (int q = gw; q < Q; q += step) {
        int n0 = q << 2;

        // ---- stage phi + env ----
        float env[4];
        #pragma unroll
        for (int n = 0; n < 4; ++n) {
            int node = n0 + n;
            bool v = node < N;
            phis[n * 33 + lane] = v ? g_PHI[(size_t)node * 32 + lane] : 0.0f;
            env[n] = v ? g_ENV[node] : 0.0f;
        }
        __syncwarp();

        // ---- per-node: stage X, normalize, decompose -> comp planes ----
        #pragma unroll
        for (int n = 0; n < 4; ++n) {
            int node = n0 + n;
            if (node < N) {
                const float4* src = (const float4*)(X + (size_t)node * 576);
                float4* dst = (float4*)xs;
                #pragma unroll
                for (int i = 0; i < 5; ++i) {
                    int idx = lane + 32 * i;
                    if (idx < 144) dst[idx] = src[idx];
                }
            }
            __syncwarp();
            float* cpn = cp + n * CPSZ;
            #pragma unroll
            for (int h = 0; h < 2; ++h) {
                int c = lane + 32 * h;
                float x[9];
                #pragma unroll
                for (int k = 0; k < 9; ++k) x[k] = xs[c * 9 + k];
                float f = 0.0f;
                #pragma unroll
                for (int k = 0; k < 9; ++k) f += x[k] * x[k];
                float sc = __fdividef(1.0f, f + 1.0f);
                #pragma unroll
                for (int k = 0; k < 9; ++k) x[k] *= sc;
                float iso, a[3], s[5];
                decomp9(x, &iso, a, s);
                cpn[0 * PLANE + c] = a[0];
                cpn[1 * PLANE + c] = a[1];
                cpn[2 * PLANE + c] = a[2];
                cpn[3 * PLANE + c] = s[0];
                cpn[4 * PLANE + c] = s[1];
                cpn[5 * PLANE + c] = s[2];
                cpn[6 * PLANE + c] = s[3];
                cpn[7 * PLANE + c] = s[4];
                cpn[8 * PLANE + c] = iso;
            }
            __syncwarp();
        }

        // ---- coefficient GEMV (weights shared across the 4 nodes) ----
        float fI[2][4], fA[2][4], fS[2][4];
        #pragma unroll
        for (int n = 0; n < 4; ++n) {
            fI[0][n] = env[n] * bI0; fI[1][n] = env[n] * bI1;
            fA[0][n] = env[n] * bA0; fA[1][n] = env[n] * bA1;
            fS[0][n] = env[n] * bS0; fS[1][n] = env[n] * bS1;
        }
        #pragma unroll 4
        for (int r = 0; r < 32; ++r) {
            const float* wr = smWdT + r * 192;
            float wi0 = wr[lane],       wi1 = wr[lane + 32];
            float wa0 = wr[64 + lane],  wa1 = wr[96 + lane];
            float ws0 = wr[128 + lane], ws1 = wr[160 + lane];
            #pragma unroll
            for (int n = 0; n < 4; ++n) {
                float p = phis[n * 33 + r];
                fI[0][n] += wi0 * p; fI[1][n] += wi1 * p;
                fA[0][n] += wa0 * p; fA[1][n] += wa1 * p;
                fS[0][n] += ws0 * p; fS[1][n] += ws1 * p;
            }
        }

        // ---- pre mixes (sector-split) ----
        float yi[2][4], ya[3][2][4], ys[5][2][4];
        {
            unsigned long long accA[3][2][4] = {};
            sector_pass<3>(smWA_a, cp, lane, accA);
            #pragma unroll
            for (int k = 0; k < 3; ++k)
                #pragma unroll
                for (int h = 0; h < 2; ++h)
                    #pragma unroll
                    for (int n = 0; n < 4; ++n) ya[k][h][n] = sum2(accA[k][h][n]);
        }
        {
            unsigned long long accS[5][2][4] = {};
            sector_pass<5>(smWS_a, cp + 3 * PLANE, lane, accS);
            #pragma unroll
            for (int k = 0; k < 5; ++k)
                #pragma unroll
                for (int h = 0; h < 2; ++h)
                    #pragma unroll
                    for (int n = 0; n < 4; ++n) ys[k][h][n] = sum2(accS[k][h][n]);
        }
        {
            unsigned long long accI[1][2][4] = {};
            sector_pass<1>(smWI_a, cp + 8 * PLANE, lane, accI);
            #pragma unroll
            for (int h = 0; h < 2; ++h)
                #pragma unroll
                for (int n = 0; n < 4; ++n) yi[h][n] = sum2(accI[0][h][n]);
        }
        __syncwarp();

        // ---- sandwich: Z = YM + MY, normalize, decompose -> overwrite comps
        #pragma unroll
        for (int n = 0; n < 4; ++n) {
            float* cpn = cp + n * CPSZ;
            #pragma unroll
            for (int h = 0; h < 2; ++h) {
                int c = lane + 32 * h;
                float Y[9], M[9];
                float av[3] = {ya[0][h][n], ya[1][h][n], ya[2][h][n]};
                float sv[5] = {ys[0][h][n], ys[1][h][n], ys[2][h][n],
                               ys[3][h][n], ys[4][h][n]};
                build9(yi[h][n], av, sv, Y);
                float mi = fI[h][n] * cpn[8 * PLANE + c];
                float A[3] = {fA[h][n] * cpn[0 * PLANE + c],
                              fA[h][n] * cpn[1 * PLANE + c],
                              fA[h][n] * cpn[2 * PLANE + c]};
                float S[5] = {fS[h][n] * cpn[3 * PLANE + c],
                              fS[h][n] * cpn[4 * PLANE + c],
                              fS[h][n] * cpn[5 * PLANE + c],
                              fS[h][n] * cpn[6 * PLANE + c],
                              fS[h][n] * cpn[7 * PLANE + c]};
                build9(mi, A, S, M);
                float Z[9];
                #pragma unroll
                for (int i = 0; i < 3; ++i)
                    #pragma unroll
                    for (int jj = 0; jj < 3; ++jj) {
                        float acc = 0.0f;
                        #pragma unroll
                        for (int k = 0; k < 3; ++k)
                            acc += Y[i * 3 + k] * M[k * 3 + jj]
                                 + M[i * 3 + k] * Y[k * 3 + jj];
                        Z[i * 3 + jj] = acc;
                    }
                float nrm = 0.0f;
                #pragma unroll
                for (int k = 0; k < 9; ++k) { float v = Z[k] + 1.0f; nrm += v * v; }
                float inv = __fdividef(1.0f, nrm);
                #pragma unroll
                for (int k = 0; k < 9; ++k) Z[k] *= inv;
                float iso, a2[3], s2[5];
                decomp9(Z, &iso, a2, s2);
                cpn[0 * PLANE + c] = a2[0];
                cpn[1 * PLANE + c] = a2[1];
                cpn[2 * PLANE + c] = a2[2];
                cpn[3 * PLANE + c] = s2[0];
                cpn[4 * PLANE + c] = s2[1];
                cpn[5 * PLANE + c] = s2[2];
                cpn[6 * PLANE + c] = s2[3];
                cpn[7 * PLANE + c] = s2[4];
                cpn[8 * PLANE + c] = iso;
            }
        }
        __syncwarp();

        // ---- post mixes ----
        {
            unsigned long long accA[3][2][4] = {};
            sector_pass<3>(smWA_b, cp, lane, accA);
            #pragma unroll
            for (int k = 0; k < 3; ++k)
                #pragma unroll
                for (int h = 0; h < 2; ++h)
                    #pragma unroll
                    for (int n = 0; n < 4; ++n) ya[k][h][n] = sum2(accA[k][h][n]);
        }
        {
            unsigned long long accS[5][2][4] = {};
            sector_pass<5>(smWS_b, cp + 3 * PLANE, lane, accS);
            #pragma unroll
            for (int k = 0; k < 5; ++k)
                #pragma unroll
                for (int h = 0; h < 2; ++h)
                    #pragma unroll
                    for (int n = 0; n < 4; ++n) ys[k][h][n] = sum2(accS[k][h][n]);
        }
        {
            unsigned long long accI[1][2][4] = {};
            sector_pass<1>(smWI_b, cp + 8 * PLANE, lane, accI);
            #pragma unroll
            for (int h = 0; h < 2; ++h)
                #pragma unroll
                for (int n = 0; n < 4; ++n) yi[h][n] = sum2(accI[0][h][n]);
        }
        __syncwarp();

        // ---- output: O = Y2 + Y2@Y2, stage per node, store coalesced ----
        #pragma unroll
        for (int n = 0; n < 4; ++n) {
            int node = n0 + n;
            #pragma unroll
            for (int h = 0; h < 2; ++h) {
                int c = lane + 32 * h;
                float av[3] = {ya[0][h][n], ya[1][h][n], ya[2][h][n]};
                float sv[5] = {ys[0][h][n], ys[1][h][n], ys[2][h][n],
                               ys[3][h][n], ys[4][h][n]};
                float Y2[9];
                build9(yi[h][n], av, sv, Y2);
                float* od = xs + c * 9;
                #pragma unroll
                for (int i = 0; i < 3; ++i)
                    #pragma unroll
                    for (int jj = 0; jj < 3; ++jj) {
                        float acc = Y2[i * 3 + jj];
                        #pragma unroll
                        for (int k = 0; k < 3; ++k)
                            acc += Y2[i * 3 + k] * Y2[k * 3 + jj];
                        od[i * 3 + jj] = acc;
                    }
            }
            __syncwarp();
            if (node < N) {
                float4* dst = (float4*)(out + (size_t)node * 576);
                const float4* src = (const float4*)xs;
                #pragma unroll
                for (int i = 0; i < 5; ++i) {
                    int idx = lane + 32 * i;
                    if (idx < 144) dst[idx] = src[idx];
                }
            }
            __syncwarp();
        }
    }
}

// ---------------------------------------------------------------------------
extern "C" void kernel_launch(void* const* d_in, const int* in_sizes, int n_in,
                              void* d_out, int out_size)
{
    const float* X    = (const float*)d_in[0];
    const float* dist = (const float*)d_in[1];
    const int*   nb   = (const int*)d_in[2];
    const float* WIa  = (const float*)d_in[3];
    const float* WAa  = (const float*)d_in[4];
    const float* WSa  = (const float*)d_in[5];
    const float* WIb  = (const float*)d_in[6];
    const float* WAb  = (const float*)d_in[7];
    const float* WSb  = (const float*)d_in[8];
    const float* Wd   = (const float*)d_in[9];
    const float* bd   = (const float*)d_in[10];
    float* out = (float*)d_out;

    int N = in_sizes[0] / 576;
    int E = in_sizes[1];

    void* phi_ptr = nullptr;
    void* env_ptr = nullptr;
    cudaGetSymbolAddress(&phi_ptr, g_PHI);
    cudaGetSymbolAddress(&env_ptr, g_ENV);
    cudaMemsetAsync(phi_ptr, 0, sizeof(float) * (size_t)N * 32, 0);
    cudaMemsetAsync(env_ptr, 0, sizeof(float) * (size_t)N, 0);

    double e5    = exp(-5.0);
    double delta = (1.0 - e5) / 31.0;
    double bb    = (2.0 / 32.0) * (1.0 - e5);
    double beta  = 1.0 / (bb * bb);
    float  c2    = (float)(2.0 * beta * delta);
    float  qf    = (float)exp(-2.0 * beta * delta * delta);

    edge_kernel<<<(E + 255) / 256, 256>>>(dist, nb, E,
        (float)e5, (float)delta, (float)(1.0 / delta), (float)beta, c2, qf);

    static int smem_set = 0;
    if (!smem_set) {
        cudaFuncSetAttribute(node_kernel,
                             cudaFuncAttributeMaxDynamicSharedMemorySize,
                             SMEM_FLOATS * sizeof(float));
        smem_set = 1;
    }
    node_kernel<<<148, 256, SMEM_FLOATS * sizeof(float)>>>(
        X, WIa, WAa, WSa, WIb, WAb, WSb, Wd, bd, out, N);
}

// round 8
// speedup vs baseline: 1.5157x; 1.5128x over previous
#include <cuda_runtime.h>
#include <cmath>

#define NMAX 20000

__device__ float g_PHI[NMAX * 32];
__device__ float g_ENV[NMAX];

// ---------------------------------------------------------------------------
// Edge kernel (R4-proven artifact): scatter env-weighted RBF vector + env.
// Recurrence from nearest center, scalar atomics, no local memory.
// ---------------------------------------------------------------------------
__global__ void edge_kernel(const float* __restrict__ dist,
                            const int* __restrict__ nb, int E,
                            float mu0, float delta, float inv_delta,
                            float beta, float c2, float q)
{
    int e = blockIdx.x * blockDim.x + threadIdx.x;
    if (e >= E) return;
    float d = dist[e];
    int j = nb[e];
    float env = 0.0f;
    if (d < 5.0f) env = 0.5f * (__cosf(0.62831853071795864769f * d) + 1.0f);
    atomicAdd(&g_ENV[j], env);

    float t = __expf(-d);
    int r0 = (int)floorf((t - mu0) * inv_delta + 0.5f);
    r0 = max(0, min(31, r0));
    float u0 = t - (mu0 + delta * (float)r0);
    float p0 = env * __expf(-beta * u0 * u0);
    float* phr = g_PHI + (size_t)j * 32;
    const float THR = 1e-6f;
    if (p0 > THR) atomicAdd(&phr[r0], p0);

    float w = __expf(c2 * (t - (mu0 + delta * ((float)r0 + 0.5f))));
    float p = p0;
    for (int r = r0 + 1; r < 32; ++r) {
        p *= w; w *= q;
        if (p <= THR) break;
        atomicAdd(&phr[r], p);
    }
    w = __expf(-c2 * (t - (mu0 + delta * ((float)r0 - 0.5f))));
    p = p0;
    for (int r = r0 - 1; r >= 0; --r) {
        p *= w; w *= q;
        if (p <= THR) break;
        atomicAdd(&phr[r], p);
    }
}

// ---------------------------------------------------------------------------
// f32x2 packed FMA helpers
// ---------------------------------------------------------------------------
__device__ __forceinline__ void ffma2(unsigned long long& d,
                                      unsigned long long a,
                                      unsigned long long b)
{
    asm("fma.rn.f32x2 %0, %1, %2, %0;" : "+l"(d) : "l"(a), "l"(b));
}
__device__ __forceinline__ float sum2(unsigned long long v)
{
    float lo, hi;
    asm("mov.b64 {%0, %1}, %2;" : "=f"(lo), "=f"(hi) : "l"(v));
    return lo + hi;
}

__device__ __forceinline__ void decomp9(const float x[9], float* iso,
                                        float a[3], float s[5])
{
    float m = (x[0] + x[4] + x[8]) * (1.0f / 3.0f);
    *iso = m;
    a[0] = 0.5f * (x[1] - x[3]);
    a[1] = 0.5f * (x[2] - x[6]);
    a[2] = 0.5f * (x[5] - x[7]);
    s[0] = x[0] - m;
    s[1] = 0.5f * (x[1] + x[3]);
    s[2] = 0.5f * (x[2] + x[6]);
    s[3] = x[4] - m;
    s[4] = 0.5f * (x[5] + x[7]);
}

__device__ __forceinline__ void build9(float iso, const float a[3],
                                       const float s[5], float Y[9])
{
    Y[0] = iso + s[0];        Y[1] = a[0] + s[1];       Y[2] = a[1] + s[2];
    Y[3] = s[1] - a[0];       Y[4] = iso + s[3];        Y[5] = a[2] + s[4];
    Y[6] = s[2] - a[1];       Y[7] = s[4] - a[2];       Y[8] = iso - s[0] - s[3];
}

// ---------------------------------------------------------------------------
// Node kernel: 12 warps = 6 warp-PAIRS per block; a pair shares 4 nodes.
// Each warp owns 32 output channels (one per lane): halves per-thread
// accumulator/live state vs R4 -> fits 170-reg cap at 384 threads (no spills),
// 1.5x occupancy. Pair-scoped named barriers order comp-plane reuse.
// ---------------------------------------------------------------------------
#define NWARP 12
#define NPAIR 6
#define WROW 68
#define PLANE 68
#define CPSZ (9 * PLANE)            // 612 per node
#define OFF_W    0                  // 6 * 64 * 68 = 26112
#define OFF_WDT  26112              // WdT[32][192] = 6144
#define OFF_PAIR 32256
#define PSZ      3160               // cp 4*612=2448 | xs 576 | phi 4*33=132 | pad
#define SMEM_FLOATS (OFF_PAIR + NPAIR * PSZ)   // 51,216 floats = 204,864 B

#define PAIR_BAR() asm volatile("bar.sync %0, 64;" :: "r"(barid) : "memory")

template<int NC>
__device__ __forceinline__ void sector_pass(const float* __restrict__ Wsec,
                                            const float* __restrict__ cp,
                                            int c,
                                            unsigned long long acc[NC][4])
{
    const float* w = Wsec + c * WROW;
    #pragma unroll 4
    for (int j = 0; j < 16; ++j) {
        ulonglong2 wv = *(const ulonglong2*)(w + 4 * j);
        #pragma unroll
        for (int n = 0; n < 4; ++n) {
            const float* base = cp + n * CPSZ + 4 * j;
            #pragma unroll
            for (int k = 0; k < NC; ++k) {
                ulonglong2 m = *(const ulonglong2*)(base + k * PLANE);
                ffma2(acc[k][n], wv.x, m.x);
                ffma2(acc[k][n], wv.y, m.y);
            }
        }
    }
}

__global__ __launch_bounds__(384, 1)
void node_kernel(const float* __restrict__ X,
    const float* __restrict__ WIa, const float* __restrict__ WAa, const float* __restrict__ WSa,
    const float* __restrict__ WIb, const float* __restrict__ WAb, const float* __restrict__ WSb,
    const float* __restrict__ Wd, const float* __restrict__ bd,
    float* __restrict__ out, int N)
{
    extern __shared__ float sm[];
    int tid   = threadIdx.x;
    int warp  = tid >> 5;
    int lane  = tid & 31;
    int pair  = warp >> 1;
    int half  = warp & 1;
    int c     = lane + 32 * half;     // this thread's output channel
    int pid   = tid & 63;             // id within pair
    int barid = pair + 1;             // named barrier per pair (1..6)

    // ---- stage weights (once per block), A,S,I order ----
    {
        const float* Ws[6] = {WAa, WSa, WIa, WAb, WSb, WIb};
        #pragma unroll
        for (int m = 0; m < 6; ++m) {
            const float* src = Ws[m];
            float* dst = sm + OFF_W + m * (64 * WROW);
            for (int idx = tid; idx < 4096; idx += 384)
                dst[(idx >> 6) * WROW + (idx & 63)] = src[idx];
        }
        for (int idx = tid; idx < 6144; idx += 384) {
            int gc = idx >> 5, r = idx & 31;
            sm[OFF_WDT + r * 192 + gc] = Wd[idx];
        }
    }
    // bias hoist (constant over nodes; one channel per thread)
    float bI = bd[c], bA = bd[64 + c], bS = bd[128 + c];
    __syncthreads();

    float* cp   = sm + OFF_PAIR + pair * PSZ;     // 4 * 612
    float* xs   = cp + 4 * CPSZ;                   // 576
    float* phis = xs + 576;                        // 4 * 33

    const float* smWA_a = sm + OFF_W + 0 * (64 * WROW);
    const float* smWS_a = sm + OFF_W + 1 * (64 * WROW);
    const float* smWI_a = sm + OFF_W + 2 * (64 * WROW);
    const float* smWA_b = sm + OFF_W + 3 * (64 * WROW);
    const float* smWS_b = sm + OFF_W + 4 * (64 * WROW);
    const float* smWI_b = sm + OFF_W + 5 * (64 * WROW);
    const float* smWdT  = sm + OFF_WDT;

    int Q = (N + 3) >> 2;
    int gp = blockIdx.x * NPAIR + pair;
    int step = gridDim.x * NPAIR;

    for (int q = gp; q < Q; q += step) {
        int n0 = q << 2;

        // ---- stage phi (each warp stages 2 of the 4 nodes) + env ----
        #pragma unroll
        for (int t = 0; t < 2; ++t) {
            int n = half * 2 + t;
            int node = n0 + n;
            bool v = node < N;
            phis[n * 33 + lane] = v ? g_PHI[(size_t)node * 32 + lane] : 0.0f;
        }
        float env[4];
        #pragma unroll
        for (int n = 0; n < 4; ++n) {
            int node = n0 + n;
            env[n] = (node < N) ? g_ENV[node] : 0.0f;
        }

        // ---- per node: pair-cooperative stage X, decompose own channel ----
        #pragma unroll
        for (int n = 0; n < 4; ++n) {
            int node = n0 + n;
            if (node < N) {
                const float4* src = (const float4*)(X + (size_t)node * 576);
                float4* dst = (float4*)xs;
                #pragma unroll
                for (int i = 0; i < 3; ++i) {
                    int idx = pid + 64 * i;
                    if (idx < 144) dst[idx] = src[idx];
                }
            }
            PAIR_BAR();
            if (node < N) {
                float x[9];
                #pragma unroll
                for (int k = 0; k < 9; ++k) x[k] = xs[c * 9 + k];
                float f = 0.0f;
                #pragma unroll
                for (int k = 0; k < 9; ++k) f += x[k] * x[k];
                float sc = __fdividef(1.0f, f + 1.0f);
                #pragma unroll
                for (int k = 0; k < 9; ++k) x[k] *= sc;
                float iso, a[3], s[5];
                decomp9(x, &iso, a, s);
                float* cpn = cp + n * CPSZ;
                cpn[0 * PLANE + c] = a[0];
                cpn[1 * PLANE + c] = a[1];
                cpn[2 * PLANE + c] = a[2];
                cpn[3 * PLANE + c] = s[0];
                cpn[4 * PLANE + c] = s[1];
                cpn[5 * PLANE + c] = s[2];
                cpn[6 * PLANE + c] = s[3];
                cpn[7 * PLANE + c] = s[4];
                cpn[8 * PLANE + c] = iso;
            }
            PAIR_BAR();
        }

        // ---- coefficient GEMV (one channel per thread, 4 nodes) ----
        float fI[4], fA[4], fS[4];
        #pragma unroll
        for (int n = 0; n < 4; ++n) {
            fI[n] = env[n] * bI;
            fA[n] = env[n] * bA;
            fS[n] = env[n] * bS;
        }
        #pragma unroll 4
        for (int r = 0; r < 32; ++r) {
            const float* wr = smWdT + r * 192;
            float wi = wr[c], wa = wr[64 + c], ws = wr[128 + c];
            #pragma unroll
            for (int n = 0; n < 4; ++n) {
                float p = phis[n * 33 + r];
                fI[n] += wi * p;
                fA[n] += wa * p;
                fS[n] += ws * p;
            }
        }

        // ---- pre mixes (sector-split; 32 out-channels per warp) ----
        float yi[4], ya[3][4], ys[5][4];
        {
            unsigned long long accA[3][4] = {};
            sector_pass<3>(smWA_a, cp, c, accA);
            #pragma unroll
            for (int k = 0; k < 3; ++k)
                #pragma unroll
                for (int n = 0; n < 4; ++n) ya[k][n] = sum2(accA[k][n]);
        }
        {
            unsigned long long accS[5][4] = {};
            sector_pass<5>(smWS_a, cp + 3 * PLANE, c, accS);
            #pragma unroll
            for (int k = 0; k < 5; ++k)
                #pragma unroll
                for (int n = 0; n < 4; ++n) ys[k][n] = sum2(accS[k][n]);
        }
        {
            unsigned long long accI[1][4] = {};
            sector_pass<1>(smWI_a, cp + 8 * PLANE, c, accI);
            #pragma unroll
            for (int n = 0; n < 4; ++n) yi[n] = sum2(accI[0][n]);
        }
        PAIR_BAR();   // everyone done reading comps before sandwich overwrite

        // ---- sandwich: Z = YM + MY, normalize, decompose -> overwrite comps
        #pragma unroll
        for (int n = 0; n < 4; ++n) {
            float* cpn = cp + n * CPSZ;
            float Y[9], M[9];
            float av[3] = {ya[0][n], ya[1][n], ya[2][n]};
            float sv[5] = {ys[0][n], ys[1][n], ys[2][n], ys[3][n], ys[4][n]};
            build9(yi[n], av, sv, Y);
            float mi = fI[n] * cpn[8 * PLANE + c];
            float A[3] = {fA[n] * cpn[0 * PLANE + c],
                          fA[n] * cpn[1 * PLANE + c],
                          fA[n] * cpn[2 * PLANE + c]};
            float S[5] = {fS[n] * cpn[3 * PLANE + c],
                          fS[n] * cpn[4 * PLANE + c],
                          fS[n] * cpn[5 * PLANE + c],
                          fS[n] * cpn[6 * PLANE + c],
                          fS[n] * cpn[7 * PLANE + c]};
            build9(mi, A, S, M);
            float Z[9];
            #pragma unroll
            for (int i = 0; i < 3; ++i)
                #pragma unroll
                for (int jj = 0; jj < 3; ++jj) {
                    float acc = 0.0f;
                    #pragma unroll
                    for (int k = 0; k < 3; ++k)
                        acc += Y[i * 3 + k] * M[k * 3 + jj]
                             + M[i * 3 + k] * Y[k * 3 + jj];
                    Z[i * 3 + jj] = acc;
                }
            float nrm = 0.0f;
            #pragma unroll
            for (int k = 0; k < 9; ++k) { float v = Z[k] + 1.0f; nrm += v * v; }
            float inv = __fdividef(1.0f, nrm);
            #pragma unroll
            for (int k = 0; k < 9; ++k) Z[k] *= inv;
            float iso, a2[3], s2[5];
            decomp9(Z, &iso, a2, s2);
            cpn[0 * PLANE + c] = a2[0];
            cpn[1 * PLANE + c] = a2[1];
            cpn[2 * PLANE + c] = a2[2];
            cpn[3 * PLANE + c] = s2[0];
            cpn[4 * PLANE + c] = s2[1];
            cpn[5 * PLANE + c] = s2[2];
            cpn[6 * PLANE + c] = s2[3];
            cpn[7 * PLANE + c] = s2[4];
            cpn[8 * PLANE + c] = iso;
        }
        PAIR_BAR();   // sandwich writes visible before post mixes

        // ---- post mixes ----
        {
            unsigned long long accA[3][4] = {};
            sector_pass<3>(smWA_b, cp, c, accA);
            #pragma unroll
            for (int k = 0; k < 3; ++k)
                #pragma unroll
                for (int n = 0; n < 4; ++n) ya[k][n] = sum2(accA[k][n]);
        }
        {
            unsigned long long accS[5][4] = {};
            sector_pass<5>(smWS_b, cp + 3 * PLANE, c, accS);
            #pragma unroll
            for (int k = 0; k < 5; ++k)
                #pragma unroll
                for (int n = 0; n < 4; ++n) ys[k][n] = sum2(accS[k][n]);
        }
        {
            unsigned long long accI[1][4] = {};
            sector_pass<1>(smWI_b, cp + 8 * PLANE, c, accI);
            #pragma unroll
            for (int n = 0; n < 4; ++n) yi[n] = sum2(accI[0][n]);
        }

        // ---- output: O = Y2 + Y2@Y2, stage per node, pair-coalesced store --
        #pragma unroll
        for (int n = 0; n < 4; ++n) {
            int node = n0 + n;
            {
                float av[3] = {ya[0][n], ya[1][n], ya[2][n]};
                float sv[5] = {ys[0][n], ys[1][n], ys[2][n], ys[3][n], ys[4][n]};
                float Y2[9];
                build9(yi[n], av, sv, Y2);
                float* od = xs + c * 9;
                #pragma unroll
                for (int i = 0; i < 3; ++i)
                    #pragma unroll
                    for (int jj = 0; jj < 3; ++jj) {
                        float acc = Y2[i * 3 + jj];
                        #pragma unroll
                        for (int k = 0; k < 3; ++k)
                            acc += Y2[i * 3 + k] * Y2[k * 3 + jj];
                        od[i * 3 + jj] = acc;
                    }
            }
            PAIR_BAR();
            if (node < N) {
                float4* dst = (float4*)(out + (size_t)node * 576);
                const float4* src = (const float4*)xs;
                #pragma unroll
                for (int i = 0; i < 3; ++i) {
                    int idx = pid + 64 * i;
                    if (idx < 144) dst[idx] = src[idx];
                }
            }
            PAIR_BAR();
        }
    }
}

// ---------------------------------------------------------------------------
extern "C" void kernel_launch(void* const* d_in, const int* in_sizes, int n_in,
                              void* d_out, int out_size)
{
    const float* X    = (const float*)d_in[0];
    const float* dist = (const float*)d_in[1];
    const int*   nb   = (const int*)d_in[2];
    const float* WIa  = (const float*)d_in[3];
    const float* WAa  = (const float*)d_in[4];
    const float* WSa  = (const float*)d_in[5];
    const float* WIb  = (const float*)d_in[6];
    const float* WAb  = (const float*)d_in[7];
    const float* WSb  = (const float*)d_in[8];
    const float* Wd   = (const float*)d_in[9];
    const float* bd   = (const float*)d_in[10];
    float* out = (float*)d_out;

    int N = in_sizes[0] / 576;
    int E = in_sizes[1];

    void* phi_ptr = nullptr;
    void* env_ptr = nullptr;
    cudaGetSymbolAddress(&phi_ptr, g_PHI);
    cudaGetSymbolAddress(&env_ptr, g_ENV);
    cudaMemsetAsync(phi_ptr, 0, sizeof(float) * (size_t)N * 32, 0);
    cudaMemsetAsync(env_ptr, 0, sizeof(float) * (size_t)N, 0);

    double e5    = exp(-5.0);
    double delta = (1.0 - e5) / 31.0;
    double bb    = (2.0 / 32.0) * (1.0 - e5);
    double beta  = 1.0 / (bb * bb);
    float  c2    = (float)(2.0 * beta * delta);
    float  qf    = (float)exp(-2.0 * beta * delta * delta);

    edge_kernel<<<(E + 255) / 256, 256>>>(dist, nb, E,
        (float)e5, (float)delta, (float)(1.0 / delta), (float)beta, c2, qf);

    static int smem_set = 0;
    if (!smem_set) {
        cudaFuncSetAttribute(node_kernel,
                             cudaFuncAttributeMaxDynamicSharedMemorySize,
                             SMEM_FLOATS * sizeof(float));
        smem_set = 1;
    }
    node_kernel<<<148, 384, SMEM_FLOATS * sizeof(float)>>>(
        X, WIa, WAa, WSa, WIb, WAb, WSb, Wd, bd, out, N);
}